// round 4
// baseline (speedup 1.0000x reference)
#include <cuda_runtime.h>
#include <cuda_bf16.h>
#include <stdint.h>
#include <math.h>

#define DI __device__ __forceinline__

#define BB 1024
#define HH 2048
#define EE 1024
#define K1 3072
#define N1 8192
#define K2 2048

// ---- device scratch (plain row-major [row][k], k contiguous) ----
__device__ __align__(256) __nv_bfloat16 g_A1h[BB * K1];
__device__ __align__(256) __nv_bfloat16 g_A1l[BB * K1];
__device__ __align__(256) __nv_bfloat16 g_W1h[(size_t)N1 * K1];
__device__ __align__(256) __nv_bfloat16 g_W1l[(size_t)N1 * K1];
__device__ __align__(256) __nv_bfloat16 g_W2h[EE * K2];
__device__ __align__(256) __nv_bfloat16 g_W2l[EE * K2];
__device__ __align__(256) __nv_bfloat16 g_A2h[BB * K2];
__device__ __align__(256) __nv_bfloat16 g_A2l[BB * K2];
__device__ __align__(256) float g_P[(size_t)BB * N1];   // preact [b][n]

// ---- helpers ----
DI uint32_t smem_u32(const void* p) {
    uint32_t a;
    asm("{ .reg .u64 t; cvta.to.shared.u64 t, %1; cvt.u32.u64 %0, t; }" : "=r"(a) : "l"(p));
    return a;
}
DI void split2(float v, __nv_bfloat16* hi, __nv_bfloat16* lo) {
    __nv_bfloat16 h = __float2bfloat16(v);
    *hi = h;
    *lo = __float2bfloat16(v - __bfloat162float(h));
}
DI float sigm(float v) { return 1.0f / (1.0f + expf(-v)); }

DI void ldsm4(uint32_t* r, uint32_t addr) {
    asm volatile("ldmatrix.sync.aligned.m8n8.x4.shared.b16 {%0,%1,%2,%3}, [%4];"
                 : "=r"(r[0]), "=r"(r[1]), "=r"(r[2]), "=r"(r[3]) : "r"(addr));
}
DI void mma_bf16(float* c, const uint32_t* a, const uint32_t* b) {
    asm volatile(
        "mma.sync.aligned.m16n8k16.row.col.f32.bf16.bf16.f32 "
        "{%0,%1,%2,%3}, {%4,%5,%6,%7}, {%8,%9}, {%0,%1,%2,%3};"
        : "+f"(c[0]), "+f"(c[1]), "+f"(c[2]), "+f"(c[3])
        : "r"(a[0]), "r"(a[1]), "r"(a[2]), "r"(a[3]), "r"(b[0]), "r"(b[1]));
}

// copy R rows x 64B (32 bf16) from gmem (row stride KDIM elems) into smem rows padded to 80B
template <int R, int KDIM>
DI void cp_rows(uint32_t sdst, const __nv_bfloat16* g, int tid) {
#pragma unroll
    for (int it = 0; it < R * 4; it += 256) {
        int i = it + tid;
        int row = i >> 2, ch = i & 3;
        asm volatile("cp.async.cg.shared.global [%0], [%1], 16;"
                     :: "r"(sdst + row * 80 + ch * 16),
                        "l"((const char*)(g + (size_t)row * KDIM) + ch * 16));
    }
}

template <int BN, int KDIM>
DI void stage_cp(uint32_t sb, const __nv_bfloat16* gAh, const __nv_bfloat16* gAl,
                 const __nv_bfloat16* gWh, const __nv_bfloat16* gWl, int k0, int tid) {
    cp_rows<128, KDIM>(sb,                 gAh + k0, tid);
    cp_rows<128, KDIM>(sb + 10240,         gAl + k0, tid);
    cp_rows<BN,  KDIM>(sb + 20480,         gWh + k0, tid);
    cp_rows<BN,  KDIM>(sb + 20480 + BN * 80, gWl + k0, tid);
}

// ---- convert kernels: fp32 -> bf16 hi/lo, plain row-major ----
__global__ void k_conv_a1(const float* __restrict__ x, const float* __restrict__ h) {
    int idx = blockIdx.x * 256 + threadIdx.x;
    if (idx >= BB * K1) return;
    int b = idx / K1, k = idx - b * K1;
    float v = (k < EE) ? x[(size_t)b * EE + k] : h[(size_t)b * HH + (k - EE)];
    split2(v, &g_A1h[idx], &g_A1l[idx]);
}
__global__ void k_conv_w1(const float* __restrict__ wxi, const float* __restrict__ whi_,
                          const float* __restrict__ wxg, const float* __restrict__ whg,
                          const float* __restrict__ wxf, const float* __restrict__ whf,
                          const float* __restrict__ wxo, const float* __restrict__ who_) {
    size_t idx = (size_t)blockIdx.x * 256 + threadIdx.x;
    if (idx >= (size_t)N1 * K1) return;
    int n = (int)(idx / K1);
    int k = (int)(idx - (size_t)n * K1);
    int g = n >> 11, j = n & 2047;
    float v;
    if (k < EE) {
        const float* a = (g == 0) ? wxi : (g == 1) ? wxg : (g == 2) ? wxf : wxo;
        v = a[(size_t)j * EE + k];
    } else {
        const float* a = (g == 0) ? whi_ : (g == 1) ? whg : (g == 2) ? whf : who_;
        v = a[(size_t)j * HH + (k - EE)];
    }
    split2(v, &g_W1h[idx], &g_W1l[idx]);
}
__global__ void k_conv_w2(const float* __restrict__ why) {
    int idx = blockIdx.x * 256 + threadIdx.x;
    if (idx >= EE * K2) return;
    split2(why[idx], &g_W2h[idx], &g_W2l[idx]);
}

// ---- split-bf16 HMMA GEMM: C[128 x BN] per CTA, K in 32-wide double-buffered stages ----
// MODE 0: gates preact -> g_P[b][n] ; MODE 1: y = tanh(acc + bias[n]) -> outp[b][n]
template <int BN, int WM, int WN, int KDIM, int MODE>
__global__ void __launch_bounds__(256)
k_gemm(float* __restrict__ outp, const float* __restrict__ bias) {
    constexpr int NWM = 128 / WM;
    constexpr int MI = WM / 16, NI = WN / 8;
    constexpr int STAGE = 20480 + 2 * BN * 80;
    constexpr int S = KDIM / 32;
    constexpr int OST = MODE ? EE : N1;

    extern __shared__ char smem[];
    uint32_t sbase = smem_u32(smem);
    const int tid = threadIdx.x, lane = tid & 31, wid = tid >> 5;
    const int wm = (wid % NWM) * WM, wn = (wid / NWM) * WN;
    const int nt = blockIdx.x, mt = blockIdx.y;

    const __nv_bfloat16* gAh = (MODE == 0 ? g_A1h : g_A2h) + (size_t)mt * 128 * KDIM;
    const __nv_bfloat16* gAl = (MODE == 0 ? g_A1l : g_A2l) + (size_t)mt * 128 * KDIM;
    const __nv_bfloat16* gWh = (MODE == 0 ? g_W1h : g_W2h) + (size_t)nt * BN * KDIM;
    const __nv_bfloat16* gWl = (MODE == 0 ? g_W1l : g_W2l) + (size_t)nt * BN * KDIM;

    float acc[MI][NI][4];
#pragma unroll
    for (int mi = 0; mi < MI; mi++)
#pragma unroll
        for (int ni = 0; ni < NI; ni++)
#pragma unroll
            for (int q = 0; q < 4; q++) acc[mi][ni][q] = 0.0f;

    stage_cp<BN, KDIM>(sbase, gAh, gAl, gWh, gWl, 0, tid);
    asm volatile("cp.async.commit_group;" ::: "memory");

    for (int s = 0; s < S; ++s) {
        if (s + 1 < S) {
            stage_cp<BN, KDIM>(sbase + ((s + 1) & 1) * STAGE, gAh, gAl, gWh, gWl,
                               (s + 1) * 32, tid);
            asm volatile("cp.async.commit_group;" ::: "memory");
            asm volatile("cp.async.wait_group 1;" ::: "memory");
        } else {
            asm volatile("cp.async.wait_group 0;" ::: "memory");
        }
        __syncthreads();

        uint32_t sb = sbase + (uint32_t)(s & 1) * STAGE;
        uint32_t sAh = sb, sAl = sb + 10240;
        uint32_t sWh = sb + 20480, sWl = sb + 20480 + BN * 80;

#pragma unroll
        for (int kk = 0; kk < 2; kk++) {
            // B fragments: ldmatrix.x4 covers two n8 frags (rows = n, k contiguous)
            uint32_t wh[NI][2], wl[NI][2];
#pragma unroll
            for (int nj = 0; nj < NI; nj += 2) {
                int row = wn + nj * 8 + ((lane >> 4) << 3) + (lane & 7);
                uint32_t off = (uint32_t)row * 80 + kk * 32 + ((lane >> 3) & 1) * 16;
                uint32_t r[4];
                ldsm4(r, sWh + off);
                wh[nj][0] = r[0]; wh[nj][1] = r[1]; wh[nj + 1][0] = r[2]; wh[nj + 1][1] = r[3];
                ldsm4(r, sWl + off);
                wl[nj][0] = r[0]; wl[nj][1] = r[1]; wl[nj + 1][0] = r[2]; wl[nj + 1][1] = r[3];
            }
#pragma unroll
            for (int mi = 0; mi < MI; mi++) {
                int row = wm + mi * 16 + (lane & 15);
                uint32_t off = (uint32_t)row * 80 + kk * 32 + (lane >> 4) * 16;
                uint32_t ah[4], al[4];
                ldsm4(ah, sAh + off);
                ldsm4(al, sAl + off);
#pragma unroll
                for (int ni = 0; ni < NI; ni++) {
                    mma_bf16(acc[mi][ni], ah, wh[ni]);
                    mma_bf16(acc[mi][ni], ah, wl[ni]);
                    mma_bf16(acc[mi][ni], al, wh[ni]);
                }
            }
        }
        __syncthreads();
    }

    // epilogue: thread holds rows (lane>>2, +8), cols (lane&3)*2, +1 per m16n8 tile
#pragma unroll
    for (int mi = 0; mi < MI; mi++)
#pragma unroll
        for (int ni = 0; ni < NI; ni++) {
            int m = mt * 128 + wm + mi * 16 + (lane >> 2);
            int n = nt * BN + wn + ni * 8 + (lane & 3) * 2;
            float2 v0 = make_float2(acc[mi][ni][0], acc[mi][ni][1]);
            float2 v1 = make_float2(acc[mi][ni][2], acc[mi][ni][3]);
            if (MODE == 1) {
                float b0 = bias[n], b1 = bias[n + 1];
                v0.x = tanhf(v0.x + b0); v0.y = tanhf(v0.y + b1);
                v1.x = tanhf(v1.x + b0); v1.y = tanhf(v1.y + b1);
                *(float2*)&outp[(size_t)m * OST + n] = v0;
                *(float2*)&outp[(size_t)(m + 8) * OST + n] = v1;
            } else {
                *(float2*)&g_P[(size_t)m * OST + n] = v0;
                *(float2*)&g_P[(size_t)(m + 8) * OST + n] = v1;
            }
        }
}

// ---- pointwise gates: c_new, h_new to out; h_new hi/lo to A2 for GEMM2 ----
__global__ void k_gates(const float* __restrict__ c,
                        const float* __restrict__ Bi, const float* __restrict__ Bg,
                        const float* __restrict__ Bf, const float* __restrict__ Bo,
                        float* __restrict__ out) {
    int idx = blockIdx.x * 256 + threadIdx.x;   // b*H + j
    int b = idx >> 11, j = idx & 2047;
    const float* P = g_P + (size_t)b * N1;
    float i = sigm(P[j] + Bi[j]);
    float g = tanhf(P[2048 + j] + Bg[j]);
    float f = sigm(P[4096 + j] + Bf[j]);
    float o = sigm(P[6144 + j] + Bo[j]);
    float cn = f * c[idx] + i * g;
    float hn = o * cn;
    out[BB * EE + idx] = cn;
    out[BB * EE + BB * HH + idx] = hn;
    split2(hn, &g_A2h[idx], &g_A2l[idx]);
}

extern "C" void kernel_launch(void* const* d_in, const int* in_sizes, int n_in,
                              void* d_out, int out_size) {
    const float* x   = (const float*)d_in[0];
    const float* c   = (const float*)d_in[1];
    const float* h   = (const float*)d_in[2];
    const float* wxi = (const float*)d_in[3];
    const float* whi = (const float*)d_in[4];
    const float* Bi  = (const float*)d_in[5];
    const float* wxg = (const float*)d_in[6];
    const float* whg = (const float*)d_in[7];
    const float* Bg  = (const float*)d_in[8];
    const float* wxf = (const float*)d_in[9];
    const float* whf = (const float*)d_in[10];
    const float* Bf  = (const float*)d_in[11];
    const float* wxo = (const float*)d_in[12];
    const float* who = (const float*)d_in[13];
    const float* Bo  = (const float*)d_in[14];
    const float* why = (const float*)d_in[15];
    const float* By  = (const float*)d_in[16];
    float* out = (float*)d_out;

    const int SMEM1 = 2 * (20480 + 2 * 128 * 80);   // 81920
    const int SMEM2 = 2 * (20480 + 2 * 64 * 80);    // 61440
    cudaFuncSetAttribute(k_gemm<128, 64, 32, K1, 0>,
                         cudaFuncAttributeMaxDynamicSharedMemorySize, SMEM1);
    cudaFuncSetAttribute(k_gemm<64, 32, 32, K2, 1>,
                         cudaFuncAttributeMaxDynamicSharedMemorySize, SMEM2);

    k_conv_a1<<<(BB * K1) / 256, 256>>>(x, h);
    k_conv_w1<<<(int)(((size_t)N1 * K1) / 256), 256>>>(wxi, whi, wxg, whg, wxf, whf, wxo, who);
    k_conv_w2<<<(EE * K2) / 256, 256>>>(why);
    k_gemm<128, 64, 32, K1, 0><<<dim3(N1 / 128, BB / 128), 256, SMEM1>>>(nullptr, nullptr);
    k_gates<<<(BB * HH) / 256, 256>>>(c, Bi, Bg, Bf, Bo, out);
    k_gemm<64, 32, 32, K2, 1><<<dim3(EE / 64, BB / 128), 256, SMEM2>>>(out, By);
}

// round 5
// speedup vs baseline: 1.8491x; 1.8491x over previous
#include <cuda_runtime.h>
#include <cuda_fp16.h>
#include <stdint.h>
#include <math.h>

#define DI __device__ __forceinline__

#define BB 1024
#define HH 2048
#define EE 1024
#define K1 3072
#define N1 8192
#define K2 2048

// ---- device scratch (row-major [row][k], k contiguous, fp16) ----
__device__ __align__(256) __half g_A1[BB * K1];
__device__ __align__(256) __half g_W1[(size_t)N1 * K1];
__device__ __align__(256) __half g_W2[EE * K2];
__device__ __align__(256) __half g_A2[BB * K2];
__device__ __align__(256) float g_P[(size_t)BB * N1];   // preact [b][n]

// ---- helpers ----
DI uint32_t smem_u32(const void* p) {
    uint32_t a;
    asm("{ .reg .u64 t; cvta.to.shared.u64 t, %1; cvt.u32.u64 %0, t; }" : "=r"(a) : "l"(p));
    return a;
}
DI float sigm(float v) { return 1.0f / (1.0f + expf(-v)); }

DI void ldsm4(uint32_t* r, uint32_t addr) {
    asm volatile("ldmatrix.sync.aligned.m8n8.x4.shared.b16 {%0,%1,%2,%3}, [%4];"
                 : "=r"(r[0]), "=r"(r[1]), "=r"(r[2]), "=r"(r[3]) : "r"(addr));
}
DI void mma_f16(float* c, const uint32_t* a, const uint32_t* b) {
    asm volatile(
        "mma.sync.aligned.m16n8k16.row.col.f32.f16.f16.f32 "
        "{%0,%1,%2,%3}, {%4,%5,%6,%7}, {%8,%9}, {%0,%1,%2,%3};"
        : "+f"(c[0]), "+f"(c[1]), "+f"(c[2]), "+f"(c[3])
        : "r"(a[0]), "r"(a[1]), "r"(a[2]), "r"(a[3]), "r"(b[0]), "r"(b[1]));
}

// copy R rows x 64B (32 fp16) from gmem (row stride KDIM elems) into smem rows padded to 80B
template <int R, int KDIM>
DI void cp_rows(uint32_t sdst, const __half* g, int tid) {
#pragma unroll
    for (int it = 0; it < R * 4; it += 256) {
        int i = it + tid;
        int row = i >> 2, ch = i & 3;
        asm volatile("cp.async.cg.shared.global [%0], [%1], 16;"
                     :: "r"(sdst + row * 80 + ch * 16),
                        "l"((const char*)(g + (size_t)row * KDIM) + ch * 16));
    }
}
template <int BN, int KDIM>
DI void stage_cp(uint32_t sb, const __half* gA, const __half* gW, int k0, int tid) {
    cp_rows<128, KDIM>(sb, gA + k0, tid);
    cp_rows<BN, KDIM>(sb + 128 * 80, gW + k0, tid);
}

// ---- convert kernels: fp32 -> fp16, plain row-major ----
__global__ void k_conv_a1(const float* __restrict__ x, const float* __restrict__ h) {
    int idx = blockIdx.x * 256 + threadIdx.x;
    if (idx >= BB * K1) return;
    int b = idx / K1, k = idx - b * K1;
    float v = (k < EE) ? x[(size_t)b * EE + k] : h[(size_t)b * HH + (k - EE)];
    g_A1[idx] = __float2half(v);
}
__global__ void k_conv_w1(const float* __restrict__ wxi, const float* __restrict__ whi_,
                          const float* __restrict__ wxg, const float* __restrict__ whg,
                          const float* __restrict__ wxf, const float* __restrict__ whf,
                          const float* __restrict__ wxo, const float* __restrict__ who_) {
    size_t idx = (size_t)blockIdx.x * 256 + threadIdx.x;
    if (idx >= (size_t)N1 * K1) return;
    int n = (int)(idx / K1);
    int k = (int)(idx - (size_t)n * K1);
    int g = n >> 11, j = n & 2047;
    float v;
    if (k < EE) {
        const float* a = (g == 0) ? wxi : (g == 1) ? wxg : (g == 2) ? wxf : wxo;
        v = a[(size_t)j * EE + k];
    } else {
        const float* a = (g == 0) ? whi_ : (g == 1) ? whg : (g == 2) ? whf : who_;
        v = a[(size_t)j * HH + (k - EE)];
    }
    g_W1[idx] = __float2half(v);
}
__global__ void k_conv_w2(const float* __restrict__ why) {
    int idx = blockIdx.x * 256 + threadIdx.x;
    if (idx >= EE * K2) return;
    g_W2[idx] = __float2half(why[idx]);
}

// ---- fp16 HMMA GEMM: C[128 x BN] per CTA, BK=32, 3-stage cp.async pipeline ----
// MODE 0: gates preact -> g_P[b][n] ; MODE 1: y = tanh(acc + bias[n]) -> outp[b][n]
template <int BN, int WM, int WN, int KDIM, int MODE>
__global__ void __launch_bounds__(256)
k_gemm(float* __restrict__ outp, const float* __restrict__ bias) {
    constexpr int NWM = 128 / WM;
    constexpr int MI = WM / 16, NI = WN / 8;
    constexpr int STAGE = (128 + BN) * 80;
    constexpr int S = KDIM / 32;
    constexpr int OST = MODE ? EE : N1;

    extern __shared__ char smem[];
    uint32_t sbase = smem_u32(smem);
    const int tid = threadIdx.x, lane = tid & 31, wid = tid >> 5;
    const int wm = (wid % NWM) * WM, wn = (wid / NWM) * WN;
    const int nt = blockIdx.x, mt = blockIdx.y;

    const __half* gA = (MODE == 0 ? g_A1 : g_A2) + (size_t)mt * 128 * KDIM;
    const __half* gW = (MODE == 0 ? g_W1 : g_W2) + (size_t)nt * BN * KDIM;

    float acc[MI][NI][4];
#pragma unroll
    for (int mi = 0; mi < MI; mi++)
#pragma unroll
        for (int ni = 0; ni < NI; ni++)
#pragma unroll
            for (int q = 0; q < 4; q++) acc[mi][ni][q] = 0.0f;

    stage_cp<BN, KDIM>(sbase, gA, gW, 0, tid);
    asm volatile("cp.async.commit_group;" ::: "memory");
    stage_cp<BN, KDIM>(sbase + STAGE, gA, gW, 32, tid);
    asm volatile("cp.async.commit_group;" ::: "memory");

    for (int s = 0; s < S; ++s) {
        if (s + 2 < S) {
            int nb = (s + 2) % 3;
            stage_cp<BN, KDIM>(sbase + nb * STAGE, gA, gW, (s + 2) * 32, tid);
            asm volatile("cp.async.commit_group;" ::: "memory");
            asm volatile("cp.async.wait_group 2;" ::: "memory");
        } else {
            asm volatile("cp.async.wait_group 0;" ::: "memory");
        }
        __syncthreads();

        uint32_t sb = sbase + (uint32_t)(s % 3) * STAGE;
        uint32_t sA = sb, sW = sb + 128 * 80;

#pragma unroll
        for (int kk = 0; kk < 2; kk++) {
            uint32_t wb[NI][2];
#pragma unroll
            for (int nj = 0; nj < NI; nj += 2) {
                int row = wn + nj * 8 + ((lane >> 4) << 3) + (lane & 7);
                uint32_t off = (uint32_t)row * 80 + kk * 32 + ((lane >> 3) & 1) * 16;
                uint32_t r[4];
                ldsm4(r, sW + off);
                wb[nj][0] = r[0]; wb[nj][1] = r[1];
                wb[nj + 1][0] = r[2]; wb[nj + 1][1] = r[3];
            }
#pragma unroll
            for (int mi = 0; mi < MI; mi++) {
                int row = wm + mi * 16 + (lane & 15);
                uint32_t off = (uint32_t)row * 80 + kk * 32 + (lane >> 4) * 16;
                uint32_t af[4];
                ldsm4(af, sA + off);
#pragma unroll
                for (int ni = 0; ni < NI; ni++)
                    mma_f16(acc[mi][ni], af, wb[ni]);
            }
        }
        __syncthreads();
    }

    // epilogue: thread holds rows (lane>>2, +8), cols (lane&3)*2, +1 per m16n8 tile
#pragma unroll
    for (int mi = 0; mi < MI; mi++)
#pragma unroll
        for (int ni = 0; ni < NI; ni++) {
            int m = mt * 128 + wm + mi * 16 + (lane >> 2);
            int n = nt * BN + wn + ni * 8 + (lane & 3) * 2;
            float2 v0 = make_float2(acc[mi][ni][0], acc[mi][ni][1]);
            float2 v1 = make_float2(acc[mi][ni][2], acc[mi][ni][3]);
            if (MODE == 1) {
                float b0 = bias[n], b1 = bias[n + 1];
                v0.x = tanhf(v0.x + b0); v0.y = tanhf(v0.y + b1);
                v1.x = tanhf(v1.x + b0); v1.y = tanhf(v1.y + b1);
                *(float2*)&outp[(size_t)m * OST + n] = v0;
                *(float2*)&outp[(size_t)(m + 8) * OST + n] = v1;
            } else {
                *(float2*)&g_P[(size_t)m * OST + n] = v0;
                *(float2*)&g_P[(size_t)(m + 8) * OST + n] = v1;
            }
        }
}

// ---- pointwise gates: c_new, h_new to out; h_new fp16 to A2 for GEMM2 ----
__global__ void k_gates(const float* __restrict__ c,
                        const float* __restrict__ Bi, const float* __restrict__ Bg,
                        const float* __restrict__ Bf, const float* __restrict__ Bo,
                        float* __restrict__ out) {
    int idx = blockIdx.x * 256 + threadIdx.x;   // b*H + j
    int b = idx >> 11, j = idx & 2047;
    const float* P = g_P + (size_t)b * N1;
    float i = sigm(P[j] + Bi[j]);
    float g = tanhf(P[2048 + j] + Bg[j]);
    float f = sigm(P[4096 + j] + Bf[j]);
    float o = sigm(P[6144 + j] + Bo[j]);
    float cn = f * c[idx] + i * g;
    float hn = o * cn;
    out[BB * EE + idx] = cn;
    out[BB * EE + BB * HH + idx] = hn;
    g_A2[idx] = __float2half(hn);
}

extern "C" void kernel_launch(void* const* d_in, const int* in_sizes, int n_in,
                              void* d_out, int out_size) {
    const float* x   = (const float*)d_in[0];
    const float* c   = (const float*)d_in[1];
    const float* h   = (const float*)d_in[2];
    const float* wxi = (const float*)d_in[3];
    const float* whi = (const float*)d_in[4];
    const float* Bi  = (const float*)d_in[5];
    const float* wxg = (const float*)d_in[6];
    const float* whg = (const float*)d_in[7];
    const float* Bg  = (const float*)d_in[8];
    const float* wxf = (const float*)d_in[9];
    const float* whf = (const float*)d_in[10];
    const float* Bf  = (const float*)d_in[11];
    const float* wxo = (const float*)d_in[12];
    const float* who = (const float*)d_in[13];
    const float* Bo  = (const float*)d_in[14];
    const float* why = (const float*)d_in[15];
    const float* By  = (const float*)d_in[16];
    float* out = (float*)d_out;

    const int SMEM1 = 3 * (128 + 128) * 80;   // 61440
    const int SMEM2 = 3 * (128 + 64) * 80;    // 46080
    cudaFuncSetAttribute(k_gemm<128, 64, 32, K1, 0>,
                         cudaFuncAttributeMaxDynamicSharedMemorySize, SMEM1);
    cudaFuncSetAttribute(k_gemm<64, 32, 32, K2, 1>,
                         cudaFuncAttributeMaxDynamicSharedMemorySize, SMEM2);

    k_conv_a1<<<(BB * K1) / 256, 256>>>(x, h);
    k_conv_w1<<<(int)(((size_t)N1 * K1) / 256), 256>>>(wxi, whi, wxg, whg, wxf, whf, wxo, who);
    k_conv_w2<<<(EE * K2) / 256, 256>>>(why);
    k_gemm<128, 64, 32, K1, 0><<<dim3(N1 / 128, BB / 128), 256, SMEM1>>>(nullptr, nullptr);
    k_gates<<<(BB * HH) / 256, 256>>>(c, Bi, Bg, Bf, Bo, out);
    k_gemm<64, 32, 32, K2, 1><<<dim3(EE / 64, BB / 128), 256, SMEM2>>>(out, By);
}

// round 6
// speedup vs baseline: 2.6577x; 1.4373x over previous
#include <cuda_runtime.h>
#include <cuda_fp16.h>
#include <stdint.h>
#include <math.h>

#define DI __device__ __forceinline__

#define BB 1024
#define HH 2048
#define EE 1024
#define K1 3072
#define N1 8192
#define K2 2048

// ---- device scratch ----
__device__ __align__(256) __half g_A1[BB * K1];
__device__ __align__(256) __half g_W1[(size_t)N1 * K1];   // reused as fp32 split-K partials for GEMM2
__device__ __align__(256) __half g_W2[EE * K2];
__device__ __align__(256) __half g_A2[BB * K2];
__device__ __align__(256) float g_P[(size_t)BB * N1];     // preact [b][n]

// ---- helpers ----
DI uint32_t smem_u32(const void* p) {
    uint32_t a;
    asm("{ .reg .u64 t; cvta.to.shared.u64 t, %1; cvt.u32.u64 %0, t; }" : "=r"(a) : "l"(p));
    return a;
}
DI float sigm(float v) { return 1.0f / (1.0f + expf(-v)); }

DI void ldsm4(uint32_t* r, uint32_t addr) {
    asm volatile("ldmatrix.sync.aligned.m8n8.x4.shared.b16 {%0,%1,%2,%3}, [%4];"
                 : "=r"(r[0]), "=r"(r[1]), "=r"(r[2]), "=r"(r[3]) : "r"(addr));
}
DI void mma_f16(float* c, const uint32_t* a, const uint32_t* b) {
    asm volatile(
        "mma.sync.aligned.m16n8k16.row.col.f32.f16.f16.f32 "
        "{%0,%1,%2,%3}, {%4,%5,%6,%7}, {%8,%9}, {%0,%1,%2,%3};"
        : "+f"(c[0]), "+f"(c[1]), "+f"(c[2]), "+f"(c[3])
        : "r"(a[0]), "r"(a[1]), "r"(a[2]), "r"(a[3]), "r"(b[0]), "r"(b[1]));
}

// copy R rows x 128B (64 fp16) from gmem (row stride KDIM elems) into smem rows padded to 144B
template <int R, int KDIM>
DI void cp_rows64(uint32_t sdst, const __half* g, int tid) {
#pragma unroll
    for (int it = 0; it < R * 8; it += 256) {
        int i = it + tid;
        int row = i >> 3, ch = i & 7;
        asm volatile("cp.async.cg.shared.global [%0], [%1], 16;"
                     :: "r"(sdst + row * 144 + ch * 16),
                        "l"((const char*)(g + (size_t)row * KDIM) + ch * 16));
    }
}
template <int BN, int KDIM>
DI void stage_cp(uint32_t sb, const __half* gA, const __half* gW, int k0, int tid) {
    cp_rows64<128, KDIM>(sb, gA + k0, tid);
    cp_rows64<BN, KDIM>(sb + 128 * 144, gW + k0, tid);
}

DI uint4 pack8(float4 a, float4 b) {
    __half2 h0 = __float22half2_rn(make_float2(a.x, a.y));
    __half2 h1 = __float22half2_rn(make_float2(a.z, a.w));
    __half2 h2 = __float22half2_rn(make_float2(b.x, b.y));
    __half2 h3 = __float22half2_rn(make_float2(b.z, b.w));
    uint4 r;
    r.x = *(uint32_t*)&h0; r.y = *(uint32_t*)&h1;
    r.z = *(uint32_t*)&h2; r.w = *(uint32_t*)&h3;
    return r;
}

// ---- convert kernels: fp32 -> fp16, 8 elems/thread ----
__global__ void k_conv_a1(const float* __restrict__ x, const float* __restrict__ h) {
    int idx = blockIdx.x * 256 + threadIdx.x;          // 8-elem chunks
    if (idx >= BB * K1 / 8) return;
    int i8 = idx * 8;
    int b = i8 / K1, k = i8 - b * K1;
    const float* src = (k < EE) ? &x[(size_t)b * EE + k] : &h[(size_t)b * HH + (k - EE)];
    float4 v0 = *(const float4*)src;
    float4 v1 = *(const float4*)(src + 4);
    *(uint4*)&g_A1[i8] = pack8(v0, v1);
}
__global__ void k_conv_w1(const float* __restrict__ wxi, const float* __restrict__ whi_,
                          const float* __restrict__ wxg, const float* __restrict__ whg,
                          const float* __restrict__ wxf, const float* __restrict__ whf,
                          const float* __restrict__ wxo, const float* __restrict__ who_) {
    size_t idx = (size_t)blockIdx.x * 256 + threadIdx.x;
    if (idx >= (size_t)N1 * K1 / 8) return;
    size_t i8 = idx * 8;
    int n = (int)(i8 / K1);
    int k = (int)(i8 - (size_t)n * K1);
    int g = n >> 11, j = n & 2047;
    const float* src;
    if (k < EE) {
        const float* a = (g == 0) ? wxi : (g == 1) ? wxg : (g == 2) ? wxf : wxo;
        src = &a[(size_t)j * EE + k];
    } else {
        const float* a = (g == 0) ? whi_ : (g == 1) ? whg : (g == 2) ? whf : who_;
        src = &a[(size_t)j * HH + (k - EE)];
    }
    float4 v0 = *(const float4*)src;
    float4 v1 = *(const float4*)(src + 4);
    *(uint4*)&g_W1[i8] = pack8(v0, v1);
}
__global__ void k_conv_w2(const float* __restrict__ why) {
    int idx = blockIdx.x * 256 + threadIdx.x;
    if (idx >= EE * K2 / 8) return;
    int i8 = idx * 8;
    float4 v0 = *(const float4*)&why[i8];
    float4 v1 = *(const float4*)&why[i8 + 4];
    *(uint4*)&g_W2[i8] = pack8(v0, v1);
}

// ---- fp16 HMMA GEMM: C[128 x BN] per CTA, BK=64, 3-stage ring, 1 sync/stage ----
// MODE 0: full-K gates preact -> g_P[b][n]
// MODE 1: split-K partial -> partials[z][b][n]   (z = blockIdx.z, K-chunk = S*64)
template <int BN, int WM, int WN, int S, int KDIM, int MODE>
__global__ void __launch_bounds__(256)
k_gemm(float* __restrict__ outp) {
    constexpr int NWM = 128 / WM;
    constexpr int MI = WM / 16, NI = WN / 8;
    constexpr int STAGE = (128 + BN) * 144;

    extern __shared__ char smem[];
    uint32_t sbase = smem_u32(smem);
    const int tid = threadIdx.x, lane = tid & 31, wid = tid >> 5;
    const int wm = (wid % NWM) * WM, wn = (wid / NWM) * WN;
    const int nt = blockIdx.x, mt = blockIdx.y;
    const int kOff = MODE ? blockIdx.z * (S * 64) : 0;

    const __half* gA = (MODE == 0 ? g_A1 : g_A2) + (size_t)mt * 128 * KDIM + kOff;
    const __half* gW = (MODE == 0 ? g_W1 : g_W2) + (size_t)nt * BN * KDIM + kOff;

    float acc[MI][NI][4];
#pragma unroll
    for (int mi = 0; mi < MI; mi++)
#pragma unroll
        for (int ni = 0; ni < NI; ni++)
#pragma unroll
            for (int q = 0; q < 4; q++) acc[mi][ni][q] = 0.0f;

    stage_cp<BN, KDIM>(sbase, gA, gW, 0, tid);
    asm volatile("cp.async.commit_group;" ::: "memory");
    stage_cp<BN, KDIM>(sbase + STAGE, gA, gW, 64, tid);
    asm volatile("cp.async.commit_group;" ::: "memory");

    for (int s = 0; s < S; ++s) {
        if (s + 1 < S)
            asm volatile("cp.async.wait_group 1;" ::: "memory");
        else
            asm volatile("cp.async.wait_group 0;" ::: "memory");
        __syncthreads();
        if (s + 2 < S) {
            stage_cp<BN, KDIM>(sbase + ((s + 2) % 3) * STAGE, gA, gW, (s + 2) * 64, tid);
            asm volatile("cp.async.commit_group;" ::: "memory");
        }

        uint32_t sb = sbase + (uint32_t)(s % 3) * STAGE;
        uint32_t sA = sb, sW = sb + 128 * 144;

#pragma unroll
        for (int kk = 0; kk < 4; kk++) {
            uint32_t wb[NI][2];
#pragma unroll
            for (int nj = 0; nj < NI; nj += 2) {
                int row = wn + nj * 8 + ((lane >> 4) << 3) + (lane & 7);
                uint32_t off = (uint32_t)row * 144 + kk * 32 + ((lane >> 3) & 1) * 16;
                uint32_t r[4];
                ldsm4(r, sW + off);
                wb[nj][0] = r[0]; wb[nj][1] = r[1];
                wb[nj + 1][0] = r[2]; wb[nj + 1][1] = r[3];
            }
#pragma unroll
            for (int mi = 0; mi < MI; mi++) {
                int row = wm + mi * 16 + (lane & 15);
                uint32_t off = (uint32_t)row * 144 + kk * 32 + (lane >> 4) * 16;
                uint32_t af[4];
                ldsm4(af, sA + off);
#pragma unroll
                for (int ni = 0; ni < NI; ni++)
                    mma_f16(acc[mi][ni], af, wb[ni]);
            }
        }
    }

    // epilogue
    float* dst = MODE ? (outp + (size_t)blockIdx.z * BB * EE) : g_P;
    const int OST = MODE ? EE : N1;
#pragma unroll
    for (int mi = 0; mi < MI; mi++)
#pragma unroll
        for (int ni = 0; ni < NI; ni++) {
            int m = mt * 128 + wm + mi * 16 + (lane >> 2);
            int n = nt * BN + wn + ni * 8 + (lane & 3) * 2;
            *(float2*)&dst[(size_t)m * OST + n] = make_float2(acc[mi][ni][0], acc[mi][ni][1]);
            *(float2*)&dst[(size_t)(m + 8) * OST + n] = make_float2(acc[mi][ni][2], acc[mi][ni][3]);
        }
}

// ---- pointwise gates ----
__global__ void k_gates(const float* __restrict__ c,
                        const float* __restrict__ Bi, const float* __restrict__ Bg,
                        const float* __restrict__ Bf, const float* __restrict__ Bo,
                        float* __restrict__ out) {
    int idx = blockIdx.x * 256 + threadIdx.x;   // b*H + j
    int b = idx >> 11, j = idx & 2047;
    const float* P = g_P + (size_t)b * N1;
    float i = sigm(P[j] + Bi[j]);
    float g = tanhf(P[2048 + j] + Bg[j]);
    float f = sigm(P[4096 + j] + Bf[j]);
    float o = sigm(P[6144 + j] + Bo[j]);
    float cn = f * c[idx] + i * g;
    float hn = o * cn;
    out[BB * EE + idx] = cn;
    out[BB * EE + BB * HH + idx] = hn;
    g_A2[idx] = __float2half(hn);
}

// ---- final y: reduce 4 split-K partials + bias + tanh ----
__global__ void k_y(const float* __restrict__ part, const float* __restrict__ By,
                    float* __restrict__ out) {
    int idx = blockIdx.x * 256 + threadIdx.x;   // float4 chunks
    if (idx >= BB * EE / 4) return;
    int base = idx * 4;
    int n = base & (EE - 1);
    float4 s0 = *(const float4*)&part[base];
    float4 s1 = *(const float4*)&part[(size_t)BB * EE + base];
    float4 s2 = *(const float4*)&part[(size_t)2 * BB * EE + base];
    float4 s3 = *(const float4*)&part[(size_t)3 * BB * EE + base];
    float4 bv = *(const float4*)&By[n];
    float4 r;
    r.x = tanhf(s0.x + s1.x + s2.x + s3.x + bv.x);
    r.y = tanhf(s0.y + s1.y + s2.y + s3.y + bv.y);
    r.z = tanhf(s0.z + s1.z + s2.z + s3.z + bv.z);
    r.w = tanhf(s0.w + s1.w + s2.w + s3.w + bv.w);
    *(float4*)&out[base] = r;
}

extern "C" void kernel_launch(void* const* d_in, const int* in_sizes, int n_in,
                              void* d_out, int out_size) {
    const float* x   = (const float*)d_in[0];
    const float* c   = (const float*)d_in[1];
    const float* h   = (const float*)d_in[2];
    const float* wxi = (const float*)d_in[3];
    const float* whi = (const float*)d_in[4];
    const float* Bi  = (const float*)d_in[5];
    const float* wxg = (const float*)d_in[6];
    const float* whg = (const float*)d_in[7];
    const float* Bg  = (const float*)d_in[8];
    const float* wxf = (const float*)d_in[9];
    const float* whf = (const float*)d_in[10];
    const float* Bf  = (const float*)d_in[11];
    const float* wxo = (const float*)d_in[12];
    const float* who = (const float*)d_in[13];
    const float* Bo  = (const float*)d_in[14];
    const float* why = (const float*)d_in[15];
    const float* By  = (const float*)d_in[16];
    float* out = (float*)d_out;

    float* d_part;   // split-K partials scratch: reuse g_W1 (dead after GEMM1)
    cudaGetSymbolAddress((void**)&d_part, g_W1);

    const int SMEM1 = 3 * (128 + 128) * 144;   // 110592
    const int SMEM2 = 3 * (128 + 64) * 144;    // 82944
    cudaFuncSetAttribute(k_gemm<128, 64, 32, 48, K1, 0>,
                         cudaFuncAttributeMaxDynamicSharedMemorySize, SMEM1);
    cudaFuncSetAttribute(k_gemm<64, 32, 32, 8, K2, 1>,
                         cudaFuncAttributeMaxDynamicSharedMemorySize, SMEM2);

    k_conv_a1<<<(BB * K1 / 8) / 256, 256>>>(x, h);
    k_conv_w1<<<(int)(((size_t)N1 * K1 / 8) / 256), 256>>>(wxi, whi, wxg, whg, wxf, whf, wxo, who);
    k_conv_w2<<<(EE * K2 / 8) / 256, 256>>>(why);
    k_gemm<128, 64, 32, 48, K1, 0><<<dim3(N1 / 128, BB / 128), 256, SMEM1>>>(nullptr);
    k_gates<<<(BB * HH) / 256, 256>>>(c, Bi, Bg, Bf, Bo, out);
    k_gemm<64, 32, 32, 8, K2, 1><<<dim3(EE / 64, BB / 128, 4), 256, SMEM2>>>(d_part);
    k_y<<<(BB * EE / 4) / 256, 256>>>(d_part, By, out);
}

// round 7
// speedup vs baseline: 2.9221x; 1.0995x over previous
#include <cuda_runtime.h>
#include <cuda_fp16.h>
#include <stdint.h>
#include <math.h>

#define DI __device__ __forceinline__

#define BB 1024
#define HH 2048
#define EE 1024
#define K1 3072
#define N1 8192
#define K2 2048

// ---- device scratch ----
__device__ __align__(256) __half g_A1[BB * K1];
__device__ __align__(256) __half g_W1[(size_t)N1 * K1];   // gate-interleaved rows: n' = 4*j + gate
__device__ __align__(256) __half g_W2[EE * K2];
__device__ __align__(256) __half g_A2[BB * K2];
__device__ __align__(256) float g_Part[4 * BB * EE];      // split-K partials for GEMM2

// ---- helpers ----
DI uint32_t smem_u32(const void* p) {
    uint32_t a;
    asm("{ .reg .u64 t; cvta.to.shared.u64 t, %1; cvt.u32.u64 %0, t; }" : "=r"(a) : "l"(p));
    return a;
}
DI float sigm(float v) { return 1.0f / (1.0f + expf(-v)); }

DI void ldsm4(uint32_t* r, uint32_t addr) {
    asm volatile("ldmatrix.sync.aligned.m8n8.x4.shared.b16 {%0,%1,%2,%3}, [%4];"
                 : "=r"(r[0]), "=r"(r[1]), "=r"(r[2]), "=r"(r[3]) : "r"(addr));
}
DI void mma_f16(float* c, const uint32_t* a, const uint32_t* b) {
    asm volatile(
        "mma.sync.aligned.m16n8k16.row.col.f32.f16.f16.f32 "
        "{%0,%1,%2,%3}, {%4,%5,%6,%7}, {%8,%9}, {%0,%1,%2,%3};"
        : "+f"(c[0]), "+f"(c[1]), "+f"(c[2]), "+f"(c[3])
        : "r"(a[0]), "r"(a[1]), "r"(a[2]), "r"(a[3]), "r"(b[0]), "r"(b[1]));
}

// copy R rows x 128B (64 fp16) into smem rows padded to 144B
template <int R, int KDIM>
DI void cp_rows64(uint32_t sdst, const __half* g, int tid) {
#pragma unroll
    for (int it = 0; it < R * 8; it += 256) {
        int i = it + tid;
        int row = i >> 3, ch = i & 7;
        asm volatile("cp.async.cg.shared.global [%0], [%1], 16;"
                     :: "r"(sdst + row * 144 + ch * 16),
                        "l"((const char*)(g + (size_t)row * KDIM) + ch * 16));
    }
}
template <int BN, int KDIM>
DI void stage_cp(uint32_t sb, const __half* gA, const __half* gW, int k0, int tid) {
    cp_rows64<128, KDIM>(sb, gA + k0, tid);
    cp_rows64<BN, KDIM>(sb + 128 * 144, gW + k0, tid);
}

DI uint4 pack8(float4 a, float4 b) {
    __half2 h0 = __float22half2_rn(make_float2(a.x, a.y));
    __half2 h1 = __float22half2_rn(make_float2(a.z, a.w));
    __half2 h2 = __float22half2_rn(make_float2(b.x, b.y));
    __half2 h3 = __float22half2_rn(make_float2(b.z, b.w));
    uint4 r;
    r.x = *(uint32_t*)&h0; r.y = *(uint32_t*)&h1;
    r.z = *(uint32_t*)&h2; r.w = *(uint32_t*)&h3;
    return r;
}

// ---- merged convert kernel: fp32 -> fp16, 8 elems/thread ----
#define NC_A1 (BB * K1 / 8)                       // 393216
#define NC_W1 ((int)((size_t)N1 * K1 / 8))        // 3145728
#define NC_W2 (EE * K2 / 8)                       // 262144
__global__ void k_conv(const float* __restrict__ x, const float* __restrict__ h,
                       const float* __restrict__ wxi, const float* __restrict__ whi_,
                       const float* __restrict__ wxg, const float* __restrict__ whg,
                       const float* __restrict__ wxf, const float* __restrict__ whf,
                       const float* __restrict__ wxo, const float* __restrict__ who_,
                       const float* __restrict__ why) {
    int idx = blockIdx.x * 256 + threadIdx.x;
    if (idx < NC_A1) {
        int i8 = idx * 8;
        int b = i8 / K1, k = i8 - b * K1;
        const float* src = (k < EE) ? &x[(size_t)b * EE + k] : &h[(size_t)b * HH + (k - EE)];
        *(uint4*)&g_A1[i8] = pack8(*(const float4*)src, *(const float4*)(src + 4));
    } else if (idx < NC_A1 + NC_W1) {
        size_t i8 = (size_t)(idx - NC_A1) * 8;
        int n = (int)(i8 / K1);                  // interleaved row: n = 4*j + gate
        int k = (int)(i8 - (size_t)n * K1);
        int j = n >> 2, g = n & 3;
        const float* src;
        if (k < EE) {
            const float* a = (g == 0) ? wxi : (g == 1) ? wxg : (g == 2) ? wxf : wxo;
            src = &a[(size_t)j * EE + k];
        } else {
            const float* a = (g == 0) ? whi_ : (g == 1) ? whg : (g == 2) ? whf : who_;
            src = &a[(size_t)j * HH + (k - EE)];
        }
        *(uint4*)&g_W1[i8] = pack8(*(const float4*)src, *(const float4*)(src + 4));
    } else if (idx < NC_A1 + NC_W1 + NC_W2) {
        int i8 = (idx - NC_A1 - NC_W1) * 8;
        *(uint4*)&g_W2[i8] = pack8(*(const float4*)&why[i8], *(const float4*)&why[i8 + 4]);
    }
}

// ---- fp16 HMMA GEMM, BK=64, 3-stage ring, pipelined fragments ----
// MODE 0: gate-interleaved preact + FUSED gates epilogue -> out(c_new,h_new), g_A2
// MODE 1: split-K partial -> g_Part[z][b][n]
template <int BN, int WM, int WN, int S, int KDIM, int MODE>
__global__ void __launch_bounds__(256, 2)
k_gemm(const float* __restrict__ cin,
       const float* __restrict__ Bi, const float* __restrict__ Bg,
       const float* __restrict__ Bf, const float* __restrict__ Bo,
       float* __restrict__ outp) {
    constexpr int NWM = 128 / WM;
    constexpr int MI = WM / 16, NI = WN / 8;
    constexpr int STAGE = (128 + BN) * 144;

    extern __shared__ char smem[];
    uint32_t sbase = smem_u32(smem);
    const int tid = threadIdx.x, lane = tid & 31, wid = tid >> 5;
    const int wm = (wid % NWM) * WM, wn = (wid / NWM) * WN;
    const int nt = blockIdx.x, mt = blockIdx.y;
    const int kOff = MODE ? blockIdx.z * (S * 64) : 0;

    const __half* gA = (MODE == 0 ? g_A1 : g_A2) + (size_t)mt * 128 * KDIM + kOff;
    const __half* gW = (MODE == 0 ? g_W1 : g_W2) + (size_t)nt * BN * KDIM + kOff;

    float acc[MI][NI][4];
#pragma unroll
    for (int mi = 0; mi < MI; mi++)
#pragma unroll
        for (int ni = 0; ni < NI; ni++)
#pragma unroll
            for (int q = 0; q < 4; q++) acc[mi][ni][q] = 0.0f;

    stage_cp<BN, KDIM>(sbase, gA, gW, 0, tid);
    asm volatile("cp.async.commit_group;" ::: "memory");
    stage_cp<BN, KDIM>(sbase + STAGE, gA, gW, 64, tid);
    asm volatile("cp.async.commit_group;" ::: "memory");

    // precomputed intra-tile offsets
    const uint32_t bRowOff = ((uint32_t)(((lane >> 4) << 3) + (lane & 7))) * 144
                           + ((lane >> 3) & 1) * 16;
    const uint32_t aRowOff = ((uint32_t)(lane & 15)) * 144 + (lane >> 4) * 16;

    for (int s = 0; s < S; ++s) {
        if (s + 1 < S)
            asm volatile("cp.async.wait_group 1;" ::: "memory");
        else
            asm volatile("cp.async.wait_group 0;" ::: "memory");
        __syncthreads();

        uint32_t sb = sbase + (uint32_t)(s % 3) * STAGE;
        uint32_t sA = sb + (uint32_t)wm * 144 + aRowOff;
        uint32_t sW = sb + 128 * 144 + (uint32_t)wn * 144 + bRowOff;

        uint32_t Bb[2][NI][2], Ab[2][4];
        // initial fragments for kk=0
#pragma unroll
        for (int nj = 0; nj < NI; nj += 2) {
            uint32_t r[4];
            ldsm4(r, sW + nj * 8 * 144);
            Bb[0][nj][0] = r[0]; Bb[0][nj][1] = r[1];
            Bb[0][nj + 1][0] = r[2]; Bb[0][nj + 1][1] = r[3];
        }
        ldsm4(Ab[0], sA);

        if (s + 2 < S) {
            stage_cp<BN, KDIM>(sbase + ((s + 2) % 3) * STAGE, gA, gW, (s + 2) * 64, tid);
            asm volatile("cp.async.commit_group;" ::: "memory");
        }

#pragma unroll
        for (int kk = 0; kk < 4; kk++) {
            if (kk < 3) {
#pragma unroll
                for (int nj = 0; nj < NI; nj += 2) {
                    uint32_t r[4];
                    ldsm4(r, sW + nj * 8 * 144 + (kk + 1) * 32);
                    Bb[(kk + 1) & 1][nj][0] = r[0]; Bb[(kk + 1) & 1][nj][1] = r[1];
                    Bb[(kk + 1) & 1][nj + 1][0] = r[2]; Bb[(kk + 1) & 1][nj + 1][1] = r[3];
                }
            }
#pragma unroll
            for (int mi = 0; mi < MI; mi++) {
                const int cur = (kk * MI + mi) & 1;
                if (mi + 1 < MI)
                    ldsm4(Ab[cur ^ 1], sA + (mi + 1) * 16 * 144 + kk * 32);
                else if (kk < 3)
                    ldsm4(Ab[cur ^ 1], sA + (kk + 1) * 32);
#pragma unroll
                for (int ni = 0; ni < NI; ni++)
                    mma_f16(acc[mi][ni], Ab[cur], Bb[kk & 1][ni]);
            }
        }
    }

    if (MODE == 1) {
        float* dst = g_Part + (size_t)blockIdx.z * BB * EE;
#pragma unroll
        for (int mi = 0; mi < MI; mi++)
#pragma unroll
            for (int ni = 0; ni < NI; ni++) {
                int m = mt * 128 + wm + mi * 16 + (lane >> 2);
                int n = nt * BN + wn + ni * 8 + (lane & 3) * 2;
                *(float2*)&dst[(size_t)m * EE + n] = make_float2(acc[mi][ni][0], acc[mi][ni][1]);
                *(float2*)&dst[(size_t)(m + 8) * EE + n] = make_float2(acc[mi][ni][2], acc[mi][ni][3]);
            }
    } else {
        // fused gates epilogue. smem transpose: [128 m][132 n'] floats at smem base
        // (buffers 0..1 region; safe: last stage reads only buffer (S-1)%3 = 2).
        float* sF = (float*)smem;
#pragma unroll
        for (int mi = 0; mi < MI; mi++)
#pragma unroll
            for (int ni = 0; ni < NI; ni++) {
                int ml = wm + mi * 16 + (lane >> 2);
                int nl = wn + ni * 8 + (lane & 3) * 2;
                *(float2*)&sF[ml * 132 + nl] = make_float2(acc[mi][ni][0], acc[mi][ni][1]);
                *(float2*)&sF[(ml + 8) * 132 + nl] = make_float2(acc[mi][ni][2], acc[mi][ni][3]);
            }
        __syncthreads();
        const int j = nt * 32 + lane;                     // fixed per thread
        const float bi = Bi[j], bg = Bg[j], bf = Bf[j], bo = Bo[j];
#pragma unroll 4
        for (int it = 0; it < 16; it++) {
            int ml = it * 8 + wid;
            float4 v = *(const float4*)&sF[ml * 132 + lane * 4];  // i,g,f,o preacts
            int b = mt * 128 + ml;
            float i = sigm(v.x + bi);
            float g = tanhf(v.y + bg);
            float f = sigm(v.z + bf);
            float o = sigm(v.w + bo);
            float cn = f * cin[(size_t)b * HH + j] + i * g;
            float hn = o * cn;
            outp[BB * EE + (size_t)b * HH + j] = cn;
            outp[BB * EE + BB * HH + (size_t)b * HH + j] = hn;
            g_A2[(size_t)b * HH + j] = __float2half(hn);
        }
    }
}

// ---- final y: reduce 4 split-K partials + bias + tanh ----
__global__ void k_y(const float* __restrict__ By, float* __restrict__ out) {
    int idx = blockIdx.x * 256 + threadIdx.x;
    if (idx >= BB * EE / 4) return;
    int base = idx * 4;
    int n = base & (EE - 1);
    float4 s0 = *(const float4*)&g_Part[base];
    float4 s1 = *(const float4*)&g_Part[BB * EE + base];
    float4 s2 = *(const float4*)&g_Part[2 * BB * EE + base];
    float4 s3 = *(const float4*)&g_Part[3 * BB * EE + base];
    float4 bv = *(const float4*)&By[n];
    float4 r;
    r.x = tanhf(s0.x + s1.x + s2.x + s3.x + bv.x);
    r.y = tanhf(s0.y + s1.y + s2.y + s3.y + bv.y);
    r.z = tanhf(s0.z + s1.z + s2.z + s3.z + bv.z);
    r.w = tanhf(s0.w + s1.w + s2.w + s3.w + bv.w);
    *(float4*)&out[base] = r;
}

extern "C" void kernel_launch(void* const* d_in, const int* in_sizes, int n_in,
                              void* d_out, int out_size) {
    const float* x   = (const float*)d_in[0];
    const float* c   = (const float*)d_in[1];
    const float* h   = (const float*)d_in[2];
    const float* wxi = (const float*)d_in[3];
    const float* whi = (const float*)d_in[4];
    const float* Bi  = (const float*)d_in[5];
    const float* wxg = (const float*)d_in[6];
    const float* whg = (const float*)d_in[7];
    const float* Bg  = (const float*)d_in[8];
    const float* wxf = (const float*)d_in[9];
    const float* whf = (const float*)d_in[10];
    const float* Bf  = (const float*)d_in[11];
    const float* wxo = (const float*)d_in[12];
    const float* who = (const float*)d_in[13];
    const float* Bo  = (const float*)d_in[14];
    const float* why = (const float*)d_in[15];
    const float* By  = (const float*)d_in[16];
    float* out = (float*)d_out;

    const int SMEM1 = 3 * (128 + 128) * 144;   // 110592
    const int SMEM2 = 3 * (128 + 64) * 144;    // 82944
    cudaFuncSetAttribute(k_gemm<128, 64, 32, 48, K1, 0>,
                         cudaFuncAttributeMaxDynamicSharedMemorySize, SMEM1);
    cudaFuncSetAttribute(k_gemm<64, 32, 32, 8, K2, 1>,
                         cudaFuncAttributeMaxDynamicSharedMemorySize, SMEM2);

    const int NCHUNK = NC_A1 + NC_W1 + NC_W2;
    k_conv<<<(NCHUNK + 255) / 256, 256>>>(x, h, wxi, whi, wxg, whg, wxf, whf, wxo, who, why);
    k_gemm<128, 64, 32, 48, K1, 0><<<dim3(N1 / 128, BB / 128), 256, SMEM1>>>(
        c, Bi, Bg, Bf, Bo, out);
    k_gemm<64, 32, 32, 8, K2, 1><<<dim3(EE / 64, BB / 128, 4), 256, SMEM2>>>(
        nullptr, nullptr, nullptr, nullptr, nullptr, nullptr);
    k_y<<<(BB * EE / 4) / 256, 256>>>(By, out);
}